// round 7
// baseline (speedup 1.0000x reference)
#include <cuda_runtime.h>
#include <cuda_bf16.h>
#include <cstdint>

#define N_NODES 100000
#define N_EDGES 1600000
#define D 128

// ---------------- scratch (device globals; no allocation) -------------------
__device__ float g_agg[N_NODES * D];   // aggregated neighbor features
__device__ int   g_cnt[N_NODES];       // in-degree (counts)
__device__ int   g_off[N_NODES];       // CSR row offsets
__device__ int   g_pos[N_NODES];       // fill cursors
__device__ int   g_csr[N_EDGES];       // source node per CSR slot
__device__ int   g_is64;

__device__ __forceinline__ uint32_t f2tf32(float f) {
    uint32_t r;
    asm("cvt.rna.tf32.f32 %0, %1;" : "=r"(r) : "f"(f));
    return r;
}

// ---------------------------------------------------------------------------
__global__ void detect_kernel(const int* __restrict__ ei32) {
    if (threadIdx.x == 0 && blockIdx.x == 0) {
        int allzero = 1;
        for (int i = 0; i < 64; i++)
            if (ei32[2 * i + 1] != 0) { allzero = 0; break; }
        g_is64 = allzero;
    }
}

__global__ void zero_cnt_kernel() {
    int i = blockIdx.x * blockDim.x + threadIdx.x;
    if (i < N_NODES) g_cnt[i] = 0;
}

// histogram of destination (row) indices
__global__ void hist_kernel(const void* __restrict__ ei_raw) {
    int e = blockIdx.x * blockDim.x + threadIdx.x;
    if (e >= N_EDGES) return;
    long long row = g_is64 ? ((const long long*)ei_raw)[e]
                           : (long long)((const int*)ei_raw)[e];
    if ((unsigned long long)row < N_NODES)
        atomicAdd(g_cnt + (int)row, 1);
}

// single-CTA exclusive scan of g_cnt -> g_off, g_pos
__global__ __launch_bounds__(1024) void scan_kernel() {
    __shared__ int tmp[1024];
    const int tid = threadIdx.x;
    const int CH = (N_NODES + 1023) / 1024;   // 98
    const int lo = tid * CH;
    const int hi = min(lo + CH, N_NODES);

    int sum = 0;
    for (int i = lo; i < hi; i++) sum += g_cnt[i];
    tmp[tid] = sum;
    __syncthreads();
    // Hillis-Steele inclusive scan
    for (int o = 1; o < 1024; o <<= 1) {
        int v = (tid >= o) ? tmp[tid - o] : 0;
        __syncthreads();
        tmp[tid] += v;
        __syncthreads();
    }
    int running = tmp[tid] - sum;   // exclusive prefix of this chunk
    for (int i = lo; i < hi; i++) {
        g_off[i] = running;
        g_pos[i] = running;
        running += g_cnt[i];
    }
}

// scatter source indices into CSR buckets
__global__ void fill_kernel(const void* __restrict__ ei_raw) {
    int e = blockIdx.x * blockDim.x + threadIdx.x;
    if (e >= N_EDGES) return;
    long long row, col;
    if (g_is64) {
        const long long* ei = (const long long*)ei_raw;
        row = ei[e]; col = ei[N_EDGES + e];
    } else {
        const int* ei = (const int*)ei_raw;
        row = ei[e]; col = ei[N_EDGES + e];
    }
    if ((unsigned long long)row >= N_NODES || (unsigned long long)col >= N_NODES)
        return;
    int p = atomicAdd(g_pos + (int)row, 1);
    g_csr[p] = (int)col;
}

// gather-aggregate: one warp per node, register accumulation, single store.
// Fully overwrites g_agg (no zero pass needed).
__global__ void agg_kernel(const float* __restrict__ x) {
    int n = (blockIdx.x * blockDim.x + threadIdx.x) >> 5;
    if (n >= N_NODES) return;
    const int lane = threadIdx.x & 31;
    const int start = g_off[n];
    const int cnt = g_cnt[n];

    float4 acc = make_float4(0.f, 0.f, 0.f, 0.f);
    int j = 0;
    for (; j + 2 <= cnt; j += 2) {   // unroll 2 for MLP
        int c0 = g_csr[start + j];
        int c1 = g_csr[start + j + 1];
        float4 v0 = __ldg((const float4*)(x + (long long)c0 * D + lane * 4));
        float4 v1 = __ldg((const float4*)(x + (long long)c1 * D + lane * 4));
        acc.x += v0.x + v1.x; acc.y += v0.y + v1.y;
        acc.z += v0.z + v1.z; acc.w += v0.w + v1.w;
    }
    if (j < cnt) {
        int c0 = g_csr[start + j];
        float4 v0 = __ldg((const float4*)(x + (long long)c0 * D + lane * 4));
        acc.x += v0.x; acc.y += v0.y; acc.z += v0.z; acc.w += v0.w;
    }
    *reinterpret_cast<float4*>(g_agg + (long long)n * D + lane * 4) = acc;
}

// ---------------------------------------------------------------------------
// GEMM via mma.sync.m16n8k8 tf32. out = x @ R + (invd*agg) @ W + bias.
// ---------------------------------------------------------------------------
#define PAD 132
#define SM_FLOATS (2 * 128 * PAD)

__global__ __launch_bounds__(512, 1) void gemm_mma(
    const float* __restrict__ x, const float* __restrict__ W,
    const float* __restrict__ R, const float* __restrict__ bias,
    float* __restrict__ out) {
    extern __shared__ float sm[];
    uint32_t* sA = (uint32_t*)sm;
    uint32_t* sB = (uint32_t*)(sm + 128 * PAD);

    const int t = threadIdx.x;
    const int wid = t >> 5;
    const int lane = t & 31;
    const int wm = wid >> 2;
    const int wn = wid & 3;
    const int row0 = blockIdx.x * 128;

    float c[2][4][4];
#pragma unroll
    for (int mt = 0; mt < 2; mt++)
#pragma unroll
        for (int nt = 0; nt < 4; nt++)
#pragma unroll
            for (int e = 0; e < 4; e++) c[mt][nt][e] = 0.f;

    for (int h = 0; h < 2; h++) {
        const float* Asrc = h ? g_agg : x;
        const float* Bsrc = h ? W : R;

        for (int v = t; v < 4096; v += 512) {
            int r  = v >> 5;
            int k4 = (v & 31) << 2;
            int gr = row0 + r; if (gr >= N_NODES) gr = N_NODES - 1;

            float4 av = *reinterpret_cast<const float4*>(Asrc + (long long)gr * D + k4);
            if (h) {
                float invd = 1.0f / (float)max(g_cnt[gr], 1);
                av.x *= invd; av.y *= invd; av.z *= invd; av.w *= invd;
            }
            uint4 ap = make_uint4(f2tf32(av.x), f2tf32(av.y), f2tf32(av.z), f2tf32(av.w));
            *reinterpret_cast<uint4*>(sA + r * PAD + k4) = ap;

            float4 bv = *reinterpret_cast<const float4*>(Bsrc + r * 128 + k4);
            uint4 bp = make_uint4(f2tf32(bv.x), f2tf32(bv.y), f2tf32(bv.z), f2tf32(bv.w));
            *reinterpret_cast<uint4*>(sB + r * PAD + k4) = bp;
        }
        __syncthreads();

        const int lr = lane >> 2;
        const int lk = lane & 3;
        const int arow = wm * 32 + lr;
        const int bn   = wn * 32 + lr;
#pragma unroll
        for (int kc = 0; kc < 16; kc++) {
            const int kb = kc * 8;
            uint32_t a[2][4];
#pragma unroll
            for (int mt = 0; mt < 2; mt++) {
                int r_ = arow + mt * 16;
                a[mt][0] = sA[(r_    ) * PAD + kb + lk];
                a[mt][1] = sA[(r_ + 8) * PAD + kb + lk];
                a[mt][2] = sA[(r_    ) * PAD + kb + lk + 4];
                a[mt][3] = sA[(r_ + 8) * PAD + kb + lk + 4];
            }
            uint32_t b[4][2];
#pragma unroll
            for (int nt = 0; nt < 4; nt++) {
                b[nt][0] = sB[(kb + lk    ) * PAD + bn + nt * 8];
                b[nt][1] = sB[(kb + lk + 4) * PAD + bn + nt * 8];
            }
#pragma unroll
            for (int mt = 0; mt < 2; mt++)
#pragma unroll
                for (int nt = 0; nt < 4; nt++) {
                    asm volatile(
                        "mma.sync.aligned.m16n8k8.row.col.f32.tf32.tf32.f32 "
                        "{%0,%1,%2,%3}, {%4,%5,%6,%7}, {%8,%9}, {%0,%1,%2,%3};"
                        : "+f"(c[mt][nt][0]), "+f"(c[mt][nt][1]),
                          "+f"(c[mt][nt][2]), "+f"(c[mt][nt][3])
                        : "r"(a[mt][0]), "r"(a[mt][1]), "r"(a[mt][2]), "r"(a[mt][3]),
                          "r"(b[nt][0]), "r"(b[nt][1]));
                }
        }
        __syncthreads();
    }

    const int lr = lane >> 2;
    const int lq = lane & 3;
#pragma unroll
    for (int mt = 0; mt < 2; mt++) {
#pragma unroll
        for (int nt = 0; nt < 4; nt++) {
            int cb = wn * 32 + nt * 8 + lq * 2;
            float2 bb = *reinterpret_cast<const float2*>(bias + cb);
            int r0 = row0 + wm * 32 + mt * 16 + lr;
            if (r0 < N_NODES) {
                float2 o = make_float2(c[mt][nt][0] + bb.x, c[mt][nt][1] + bb.y);
                *reinterpret_cast<float2*>(out + (long long)r0 * D + cb) = o;
            }
            int r1 = r0 + 8;
            if (r1 < N_NODES) {
                float2 o = make_float2(c[mt][nt][2] + bb.x, c[mt][nt][3] + bb.y);
                *reinterpret_cast<float2*>(out + (long long)r1 * D + cb) = o;
            }
        }
    }
}

// ---------------------------------------------------------------------------
extern "C" void kernel_launch(void* const* d_in, const int* in_sizes, int n_in,
                              void* d_out, int out_size) {
    const float* x    = (const float*)d_in[0];
    const void*  ei   = d_in[1];
    const float* W    = (const float*)d_in[2];
    const float* R    = (const float*)d_in[3];
    const float* bias = (const float*)d_in[4];
    float*       out  = (float*)d_out;

    detect_kernel<<<1, 32>>>((const int*)ei);
    zero_cnt_kernel<<<(N_NODES + 255) / 256, 256>>>();
    hist_kernel<<<(N_EDGES + 255) / 256, 256>>>(ei);
    scan_kernel<<<1, 1024>>>();
    fill_kernel<<<(N_EDGES + 255) / 256, 256>>>(ei);
    agg_kernel<<<(N_NODES * 32 + 255) / 256, 256>>>(x);

    {
        const int SMEM = SM_FLOATS * sizeof(float);   // 135,168 B
        cudaFuncSetAttribute(gemm_mma,
                             cudaFuncAttributeMaxDynamicSharedMemorySize, SMEM);
        int blocks = (N_NODES + 127) / 128;           // 782
        gemm_mma<<<blocks, 512, SMEM>>>(x, W, R, bias, out);
    }
}

// round 8
// speedup vs baseline: 1.7979x; 1.7979x over previous
#include <cuda_runtime.h>
#include <cuda_bf16.h>
#include <cstdint>

#define N_NODES 100000
#define N_EDGES 1600000
#define D 128

#define CH 128
#define NCH ((N_NODES + CH - 1) / CH)   // 782

// ---------------- scratch (device globals; no allocation) -------------------
__device__ float g_agg[N_NODES * D];
__device__ int   g_cnt[N_NODES];
__device__ int   g_off[N_NODES];
__device__ int   g_pos[N_NODES];
__device__ int   g_csr[N_EDGES];
__device__ int   g_chunk[NCH];          // per-chunk sums
__device__ int   g_chunkoff[NCH];       // exclusive chunk bases
__device__ int   g_is64;

__device__ __forceinline__ uint32_t f2tf32(float f) {
    uint32_t r;
    asm("cvt.rna.tf32.f32 %0, %1;" : "=r"(r) : "f"(f));
    return r;
}

// ---------------------------------------------------------------------------
__global__ void detect_kernel(const int* __restrict__ ei32) {
    if (threadIdx.x == 0 && blockIdx.x == 0) {
        int allzero = 1;
        for (int i = 0; i < 64; i++)
            if (ei32[2 * i + 1] != 0) { allzero = 0; break; }
        g_is64 = allzero;
    }
}

__global__ void zero_cnt_kernel() {
    int i = blockIdx.x * blockDim.x + threadIdx.x;
    if (i < N_NODES) g_cnt[i] = 0;
}

__global__ void hist_kernel(const void* __restrict__ ei_raw) {
    int e = blockIdx.x * blockDim.x + threadIdx.x;
    if (e >= N_EDGES) return;
    long long row = g_is64 ? ((const long long*)ei_raw)[e]
                           : (long long)((const int*)ei_raw)[e];
    if ((unsigned long long)row < N_NODES)
        atomicAdd(g_cnt + (int)row, 1);
}

// ---- scan stage 1: per-chunk sums (782 CTAs x 128 threads) ----
__global__ __launch_bounds__(CH) void chunk_sum_kernel() {
    const int c = blockIdx.x;
    const int t = threadIdx.x;
    const int i = c * CH + t;
    int v = (i < N_NODES) ? g_cnt[i] : 0;
#pragma unroll
    for (int o = 16; o > 0; o >>= 1) v += __shfl_down_sync(~0u, v, o);
    __shared__ int ws[CH / 32];
    if ((t & 31) == 0) ws[t >> 5] = v;
    __syncthreads();
    if (t == 0) {
        int s = 0;
#pragma unroll
        for (int w = 0; w < CH / 32; w++) s += ws[w];
        g_chunk[c] = s;
    }
}

// ---- scan stage 2: single-CTA scan of 782 chunk sums (smem) ----
__global__ __launch_bounds__(1024) void scan_chunks_kernel() {
    __shared__ int tmp[1024];
    const int t = threadIdx.x;
    int v = (t < NCH) ? g_chunk[t] : 0;
    tmp[t] = v;
    __syncthreads();
    for (int o = 1; o < 1024; o <<= 1) {
        int u = (t >= o) ? tmp[t - o] : 0;
        __syncthreads();
        tmp[t] += u;
        __syncthreads();
    }
    if (t < NCH) g_chunkoff[t] = tmp[t] - v;   // exclusive
}

// ---- scan stage 3: intra-chunk exclusive scan + base -> g_off/g_pos ----
__global__ __launch_bounds__(CH) void write_off_kernel() {
    const int c = blockIdx.x;
    const int t = threadIdx.x;
    const int i = c * CH + t;
    const int lane = t & 31;
    const int w = t >> 5;
    int v = (i < N_NODES) ? g_cnt[i] : 0;

    int inc = v;
#pragma unroll
    for (int o = 1; o < 32; o <<= 1) {
        int u = __shfl_up_sync(~0u, inc, o);
        if (lane >= o) inc += u;
    }
    __shared__ int ws[CH / 32];
    __shared__ int wo[CH / 32];
    if (lane == 31) ws[w] = inc;
    __syncthreads();
    if (t == 0) {
        int run = 0;
#pragma unroll
        for (int k = 0; k < CH / 32; k++) { wo[k] = run; run += ws[k]; }
    }
    __syncthreads();
    int ex = inc - v + wo[w] + g_chunkoff[c];
    if (i < N_NODES) { g_off[i] = ex; g_pos[i] = ex; }
}

// ---- CSR fill ----
__global__ void fill_kernel(const void* __restrict__ ei_raw) {
    int e = blockIdx.x * blockDim.x + threadIdx.x;
    if (e >= N_EDGES) return;
    long long row, col;
    if (g_is64) {
        const long long* ei = (const long long*)ei_raw;
        row = ei[e]; col = ei[N_EDGES + e];
    } else {
        const int* ei = (const int*)ei_raw;
        row = ei[e]; col = ei[N_EDGES + e];
    }
    if ((unsigned long long)row >= N_NODES || (unsigned long long)col >= N_NODES)
        return;
    int p = atomicAdd(g_pos + (int)row, 1);
    g_csr[p] = (int)col;
}

// ---- gather-aggregate: one warp per node ----
__global__ void agg_kernel(const float* __restrict__ x) {
    int n = (blockIdx.x * blockDim.x + threadIdx.x) >> 5;
    if (n >= N_NODES) return;
    const int lane = threadIdx.x & 31;
    const int start = g_off[n];
    const int cnt = g_cnt[n];

    float4 acc = make_float4(0.f, 0.f, 0.f, 0.f);
    int j = 0;
    for (; j + 2 <= cnt; j += 2) {
        int c0 = g_csr[start + j];
        int c1 = g_csr[start + j + 1];
        float4 v0 = __ldg((const float4*)(x + (long long)c0 * D + lane * 4));
        float4 v1 = __ldg((const float4*)(x + (long long)c1 * D + lane * 4));
        acc.x += v0.x + v1.x; acc.y += v0.y + v1.y;
        acc.z += v0.z + v1.z; acc.w += v0.w + v1.w;
    }
    if (j < cnt) {
        int c0 = g_csr[start + j];
        float4 v0 = __ldg((const float4*)(x + (long long)c0 * D + lane * 4));
        acc.x += v0.x; acc.y += v0.y; acc.z += v0.z; acc.w += v0.w;
    }
    *reinterpret_cast<float4*>(g_agg + (long long)n * D + lane * 4) = acc;
}

// ---------------------------------------------------------------------------
// GEMM via mma.sync.m16n8k8 tf32. out = x @ R + (invd*agg) @ W + bias.
// ---------------------------------------------------------------------------
#define PAD 132
#define SM_FLOATS (2 * 128 * PAD)

__global__ __launch_bounds__(512, 1) void gemm_mma(
    const float* __restrict__ x, const float* __restrict__ W,
    const float* __restrict__ R, const float* __restrict__ bias,
    float* __restrict__ out) {
    extern __shared__ float sm[];
    uint32_t* sA = (uint32_t*)sm;
    uint32_t* sB = (uint32_t*)(sm + 128 * PAD);

    const int t = threadIdx.x;
    const int wid = t >> 5;
    const int lane = t & 31;
    const int wm = wid >> 2;
    const int wn = wid & 3;
    const int row0 = blockIdx.x * 128;

    float c[2][4][4];
#pragma unroll
    for (int mt = 0; mt < 2; mt++)
#pragma unroll
        for (int nt = 0; nt < 4; nt++)
#pragma unroll
            for (int e = 0; e < 4; e++) c[mt][nt][e] = 0.f;

    for (int h = 0; h < 2; h++) {
        const float* Asrc = h ? g_agg : x;
        const float* Bsrc = h ? W : R;

        for (int v = t; v < 4096; v += 512) {
            int r  = v >> 5;
            int k4 = (v & 31) << 2;
            int gr = row0 + r; if (gr >= N_NODES) gr = N_NODES - 1;

            float4 av = *reinterpret_cast<const float4*>(Asrc + (long long)gr * D + k4);
            if (h) {
                float invd = 1.0f / (float)max(g_cnt[gr], 1);
                av.x *= invd; av.y *= invd; av.z *= invd; av.w *= invd;
            }
            uint4 ap = make_uint4(f2tf32(av.x), f2tf32(av.y), f2tf32(av.z), f2tf32(av.w));
            *reinterpret_cast<uint4*>(sA + r * PAD + k4) = ap;

            float4 bv = *reinterpret_cast<const float4*>(Bsrc + r * 128 + k4);
            uint4 bp = make_uint4(f2tf32(bv.x), f2tf32(bv.y), f2tf32(bv.z), f2tf32(bv.w));
            *reinterpret_cast<uint4*>(sB + r * PAD + k4) = bp;
        }
        __syncthreads();

        const int lr = lane >> 2;
        const int lk = lane & 3;
        const int arow = wm * 32 + lr;
        const int bn   = wn * 32 + lr;
#pragma unroll
        for (int kc = 0; kc < 16; kc++) {
            const int kb = kc * 8;
            uint32_t a[2][4];
#pragma unroll
            for (int mt = 0; mt < 2; mt++) {
                int r_ = arow + mt * 16;
                a[mt][0] = sA[(r_    ) * PAD + kb + lk];
                a[mt][1] = sA[(r_ + 8) * PAD + kb + lk];
                a[mt][2] = sA[(r_    ) * PAD + kb + lk + 4];
                a[mt][3] = sA[(r_ + 8) * PAD + kb + lk + 4];
            }
            uint32_t b[4][2];
#pragma unroll
            for (int nt = 0; nt < 4; nt++) {
                b[nt][0] = sB[(kb + lk    ) * PAD + bn + nt * 8];
                b[nt][1] = sB[(kb + lk + 4) * PAD + bn + nt * 8];
            }
#pragma unroll
            for (int mt = 0; mt < 2; mt++)
#pragma unroll
                for (int nt = 0; nt < 4; nt++) {
                    asm volatile(
                        "mma.sync.aligned.m16n8k8.row.col.f32.tf32.tf32.f32 "
                        "{%0,%1,%2,%3}, {%4,%5,%6,%7}, {%8,%9}, {%0,%1,%2,%3};"
                        : "+f"(c[mt][nt][0]), "+f"(c[mt][nt][1]),
                          "+f"(c[mt][nt][2]), "+f"(c[mt][nt][3])
                        : "r"(a[mt][0]), "r"(a[mt][1]), "r"(a[mt][2]), "r"(a[mt][3]),
                          "r"(b[nt][0]), "r"(b[nt][1]));
                }
        }
        __syncthreads();
    }

    const int lr = lane >> 2;
    const int lq = lane & 3;
#pragma unroll
    for (int mt = 0; mt < 2; mt++) {
#pragma unroll
        for (int nt = 0; nt < 4; nt++) {
            int cb = wn * 32 + nt * 8 + lq * 2;
            float2 bb = *reinterpret_cast<const float2*>(bias + cb);
            int r0 = row0 + wm * 32 + mt * 16 + lr;
            if (r0 < N_NODES) {
                float2 o = make_float2(c[mt][nt][0] + bb.x, c[mt][nt][1] + bb.y);
                *reinterpret_cast<float2*>(out + (long long)r0 * D + cb) = o;
            }
            int r1 = r0 + 8;
            if (r1 < N_NODES) {
                float2 o = make_float2(c[mt][nt][2] + bb.x, c[mt][nt][3] + bb.y);
                *reinterpret_cast<float2*>(out + (long long)r1 * D + cb) = o;
            }
        }
    }
}

// ---------------------------------------------------------------------------
extern "C" void kernel_launch(void* const* d_in, const int* in_sizes, int n_in,
                              void* d_out, int out_size) {
    const float* x    = (const float*)d_in[0];
    const void*  ei   = d_in[1];
    const float* W    = (const float*)d_in[2];
    const float* R    = (const float*)d_in[3];
    const float* bias = (const float*)d_in[4];
    float*       out  = (float*)d_out;

    detect_kernel<<<1, 32>>>((const int*)ei);
    zero_cnt_kernel<<<(N_NODES + 255) / 256, 256>>>();
    hist_kernel<<<(N_EDGES + 255) / 256, 256>>>(ei);
    chunk_sum_kernel<<<NCH, CH>>>();
    scan_chunks_kernel<<<1, 1024>>>();
    write_off_kernel<<<NCH, CH>>>();
    fill_kernel<<<(N_EDGES + 255) / 256, 256>>>(ei);
    agg_kernel<<<(N_NODES * 32 + 255) / 256, 256>>>(x);

    {
        const int SMEM = SM_FLOATS * sizeof(float);   // 135,168 B
        cudaFuncSetAttribute(gemm_mma,
                             cudaFuncAttributeMaxDynamicSharedMemorySize, SMEM);
        int blocks = (N_NODES + 127) / 128;           // 782
        gemm_mma<<<blocks, 512, SMEM>>>(x, W, R, bias, out);
    }
}

// round 9
// speedup vs baseline: 1.9341x; 1.0757x over previous
#include <cuda_runtime.h>
#include <cuda_bf16.h>
#include <cstdint>

#define N_NODES 100000
#define N_EDGES 1600000
#define D 128

#define CH 128
#define NCH ((N_NODES + CH - 1) / CH)   // 782

// ---------------- scratch (device globals; no allocation) -------------------
__device__ float g_agg[N_NODES * D];
__device__ int   g_cnt[N_NODES];
__device__ int   g_off[N_NODES];
__device__ int   g_pos[N_NODES];
__device__ int   g_csr[N_EDGES];
__device__ int   g_chunk[NCH];
__device__ int   g_chunkoff[NCH];
__device__ int   g_is64;

__device__ __forceinline__ void cp16(void* dst, const void* src) {
    uint32_t d = (uint32_t)__cvta_generic_to_shared(dst);
    asm volatile("cp.async.cg.shared.global [%0], [%1], 16;" :: "r"(d), "l"(src));
}

// ---------------------------------------------------------------------------
__global__ void detect_kernel(const int* __restrict__ ei32) {
    if (threadIdx.x == 0 && blockIdx.x == 0) {
        int allzero = 1;
        for (int i = 0; i < 64; i++)
            if (ei32[2 * i + 1] != 0) { allzero = 0; break; }
        g_is64 = allzero;
    }
}

__global__ void zero_cnt_kernel() {
    int i = blockIdx.x * blockDim.x + threadIdx.x;
    if (i < N_NODES) g_cnt[i] = 0;
}

__global__ void hist_kernel(const void* __restrict__ ei_raw) {
    int e = blockIdx.x * blockDim.x + threadIdx.x;
    if (e >= N_EDGES) return;
    long long row = g_is64 ? ((const long long*)ei_raw)[e]
                           : (long long)((const int*)ei_raw)[e];
    if ((unsigned long long)row < N_NODES)
        atomicAdd(g_cnt + (int)row, 1);
}

__global__ __launch_bounds__(CH) void chunk_sum_kernel() {
    const int c = blockIdx.x;
    const int t = threadIdx.x;
    const int i = c * CH + t;
    int v = (i < N_NODES) ? g_cnt[i] : 0;
#pragma unroll
    for (int o = 16; o > 0; o >>= 1) v += __shfl_down_sync(~0u, v, o);
    __shared__ int ws[CH / 32];
    if ((t & 31) == 0) ws[t >> 5] = v;
    __syncthreads();
    if (t == 0) {
        int s = 0;
#pragma unroll
        for (int w = 0; w < CH / 32; w++) s += ws[w];
        g_chunk[c] = s;
    }
}

__global__ __launch_bounds__(1024) void scan_chunks_kernel() {
    __shared__ int tmp[1024];
    const int t = threadIdx.x;
    int v = (t < NCH) ? g_chunk[t] : 0;
    tmp[t] = v;
    __syncthreads();
    for (int o = 1; o < 1024; o <<= 1) {
        int u = (t >= o) ? tmp[t - o] : 0;
        __syncthreads();
        tmp[t] += u;
        __syncthreads();
    }
    if (t < NCH) g_chunkoff[t] = tmp[t] - v;
}

__global__ __launch_bounds__(CH) void write_off_kernel() {
    const int c = blockIdx.x;
    const int t = threadIdx.x;
    const int i = c * CH + t;
    const int lane = t & 31;
    const int w = t >> 5;
    int v = (i < N_NODES) ? g_cnt[i] : 0;

    int inc = v;
#pragma unroll
    for (int o = 1; o < 32; o <<= 1) {
        int u = __shfl_up_sync(~0u, inc, o);
        if (lane >= o) inc += u;
    }
    __shared__ int ws[CH / 32];
    __shared__ int wo[CH / 32];
    if (lane == 31) ws[w] = inc;
    __syncthreads();
    if (t == 0) {
        int run = 0;
#pragma unroll
        for (int k = 0; k < CH / 32; k++) { wo[k] = run; run += ws[k]; }
    }
    __syncthreads();
    int ex = inc - v + wo[w] + g_chunkoff[c];
    if (i < N_NODES) { g_off[i] = ex; g_pos[i] = ex; }
}

__global__ void fill_kernel(const void* __restrict__ ei_raw) {
    int e = blockIdx.x * blockDim.x + threadIdx.x;
    if (e >= N_EDGES) return;
    long long row, col;
    if (g_is64) {
        const long long* ei = (const long long*)ei_raw;
        row = ei[e]; col = ei[N_EDGES + e];
    } else {
        const int* ei = (const int*)ei_raw;
        row = ei[e]; col = ei[N_EDGES + e];
    }
    if ((unsigned long long)row >= N_NODES || (unsigned long long)col >= N_NODES)
        return;
    int p = atomicAdd(g_pos + (int)row, 1);
    g_csr[p] = (int)col;
}

// ---- gather-aggregate: one warp per node, unroll 4 for MLP ----
__global__ void agg_kernel(const float* __restrict__ x) {
    int n = (blockIdx.x * blockDim.x + threadIdx.x) >> 5;
    if (n >= N_NODES) return;
    const int lane = threadIdx.x & 31;
    const int start = g_off[n];
    const int cnt = g_cnt[n];

    float4 acc = make_float4(0.f, 0.f, 0.f, 0.f);
    int j = 0;
    for (; j + 4 <= cnt; j += 4) {
        int c0 = g_csr[start + j];
        int c1 = g_csr[start + j + 1];
        int c2 = g_csr[start + j + 2];
        int c3 = g_csr[start + j + 3];
        float4 v0 = __ldg((const float4*)(x + (long long)c0 * D + lane * 4));
        float4 v1 = __ldg((const float4*)(x + (long long)c1 * D + lane * 4));
        float4 v2 = __ldg((const float4*)(x + (long long)c2 * D + lane * 4));
        float4 v3 = __ldg((const float4*)(x + (long long)c3 * D + lane * 4));
        acc.x += (v0.x + v1.x) + (v2.x + v3.x);
        acc.y += (v0.y + v1.y) + (v2.y + v3.y);
        acc.z += (v0.z + v1.z) + (v2.z + v3.z);
        acc.w += (v0.w + v1.w) + (v2.w + v3.w);
    }
    for (; j < cnt; j++) {
        int c0 = g_csr[start + j];
        float4 v0 = __ldg((const float4*)(x + (long long)c0 * D + lane * 4));
        acc.x += v0.x; acc.y += v0.y; acc.z += v0.z; acc.w += v0.w;
    }
    *reinterpret_cast<float4*>(g_agg + (long long)n * D + lane * 4) = acc;
}

// ---------------------------------------------------------------------------
// Pipelined tf32 GEMM: out = x @ R + (invd*agg) @ W + bias.
// 4 K=64 stages (x/R k0, x/R k1, agg/W k0, agg/W k1), cp.async depth-2
// double buffer, raw fp32 bits fed to tf32 MMA (HW truncates mantissa).
// invd folded into A-fragments during stages 2-3.
// ---------------------------------------------------------------------------
#define APAD 68
#define BPAD 132
#define BUF_FLOATS (128 * APAD + 64 * BPAD)   // 17152

__global__ __launch_bounds__(512, 1) void gemm_mma(
    const float* __restrict__ x, const float* __restrict__ W,
    const float* __restrict__ R, const float* __restrict__ bias,
    float* __restrict__ out) {
    extern __shared__ float sm[];

    const int t = threadIdx.x;
    const int wid = t >> 5;
    const int lane = t & 31;
    const int wm = wid >> 2;
    const int wn = wid & 3;
    const int row0 = blockIdx.x * 128;
    const int lr = lane >> 2;
    const int lk = lane & 3;
    const int arow = wm * 32 + lr;
    const int bn = wn * 32 + lr;

    // stage loader: s in 0..3
    auto load_stage = [&](int s, int buf) {
        const float* Asrc = (s < 2) ? x : g_agg;
        const float* Bsrc = (s < 2) ? R : W;
        const int koff = (s & 1) * 64;
        float* dA = sm + buf * BUF_FLOATS;
        float* dB = dA + 128 * APAD;
#pragma unroll
        for (int v = t; v < 2048; v += 512) {
            int r = v >> 4;
            int k4 = (v & 15) << 2;
            int gr = row0 + r; if (gr >= N_NODES) gr = N_NODES - 1;
            cp16(dA + r * APAD + k4, Asrc + (long long)gr * D + koff + k4);
        }
#pragma unroll
        for (int v = t; v < 2048; v += 512) {
            int kr = v >> 5;
            int n4 = (v & 31) << 2;
            cp16(dB + kr * BPAD + n4, Bsrc + (koff + kr) * 128 + n4);
        }
        asm volatile("cp.async.commit_group;");
    };

    // per-thread invd for the 4 A-fragment rows (mt in {0,1}, +0/+8)
    float ivd[2][2];
#pragma unroll
    for (int mt = 0; mt < 2; mt++)
#pragma unroll
        for (int rr = 0; rr < 2; rr++) {
            int gr = row0 + arow + mt * 16 + rr * 8;
            if (gr >= N_NODES) gr = N_NODES - 1;
            ivd[mt][rr] = 1.0f / (float)max(g_cnt[gr], 1);
        }

    float c[2][4][4];
#pragma unroll
    for (int mt = 0; mt < 2; mt++)
#pragma unroll
        for (int nt = 0; nt < 4; nt++)
#pragma unroll
            for (int e = 0; e < 4; e++) c[mt][nt][e] = 0.f;

    load_stage(0, 0);
    load_stage(1, 1);

#pragma unroll
    for (int s = 0; s < 4; s++) {
        if (s < 3) asm volatile("cp.async.wait_group 1;");
        else       asm volatile("cp.async.wait_group 0;");
        __syncthreads();

        const float* bA = sm + (s & 1) * BUF_FLOATS;
        const float* bB = bA + 128 * APAD;
        const bool scale = (s >= 2);

#pragma unroll
        for (int kc = 0; kc < 8; kc++) {
            const int kb = kc * 8;
            float af[2][4];
#pragma unroll
            for (int mt = 0; mt < 2; mt++) {
                int r_ = arow + mt * 16;
                af[mt][0] = bA[(r_    ) * APAD + kb + lk];
                af[mt][1] = bA[(r_ + 8) * APAD + kb + lk];
                af[mt][2] = bA[(r_    ) * APAD + kb + lk + 4];
                af[mt][3] = bA[(r_ + 8) * APAD + kb + lk + 4];
                if (scale) {
                    af[mt][0] *= ivd[mt][0]; af[mt][1] *= ivd[mt][1];
                    af[mt][2] *= ivd[mt][0]; af[mt][3] *= ivd[mt][1];
                }
            }
            uint32_t b[4][2];
#pragma unroll
            for (int nt = 0; nt < 4; nt++) {
                b[nt][0] = __float_as_uint(bB[(kb + lk    ) * BPAD + bn + nt * 8]);
                b[nt][1] = __float_as_uint(bB[(kb + lk + 4) * BPAD + bn + nt * 8]);
            }
#pragma unroll
            for (int mt = 0; mt < 2; mt++)
#pragma unroll
                for (int nt = 0; nt < 4; nt++) {
                    asm volatile(
                        "mma.sync.aligned.m16n8k8.row.col.f32.tf32.tf32.f32 "
                        "{%0,%1,%2,%3}, {%4,%5,%6,%7}, {%8,%9}, {%0,%1,%2,%3};"
                        : "+f"(c[mt][nt][0]), "+f"(c[mt][nt][1]),
                          "+f"(c[mt][nt][2]), "+f"(c[mt][nt][3])
                        : "r"(__float_as_uint(af[mt][0])), "r"(__float_as_uint(af[mt][1])),
                          "r"(__float_as_uint(af[mt][2])), "r"(__float_as_uint(af[mt][3])),
                          "r"(b[nt][0]), "r"(b[nt][1]));
                }
        }

        if (s + 2 < 4) {
            __syncthreads();
            load_stage(s + 2, s & 1);
        }
    }

    // ---- epilogue ----
    const int lq = lane & 3;
#pragma unroll
    for (int mt = 0; mt < 2; mt++) {
#pragma unroll
        for (int nt = 0; nt < 4; nt++) {
            int cb = wn * 32 + nt * 8 + lq * 2;
            float2 bb = *reinterpret_cast<const float2*>(bias + cb);
            int r0 = row0 + wm * 32 + mt * 16 + lr;
            if (r0 < N_NODES) {
                float2 o = make_float2(c[mt][nt][0] + bb.x, c[mt][nt][1] + bb.y);
                *reinterpret_cast<float2*>(out + (long long)r0 * D + cb) = o;
            }
            int r1 = r0 + 8;
            if (r1 < N_NODES) {
                float2 o = make_float2(c[mt][nt][2] + bb.x, c[mt][nt][3] + bb.y);
                *reinterpret_cast<float2*>(out + (long long)r1 * D + cb) = o;
            }
        }
    }
}

// ---------------------------------------------------------------------------
extern "C" void kernel_launch(void* const* d_in, const int* in_sizes, int n_in,
                              void* d_out, int out_size) {
    const float* x    = (const float*)d_in[0];
    const void*  ei   = d_in[1];
    const float* W    = (const float*)d_in[2];
    const float* R    = (const float*)d_in[3];
    const float* bias = (const float*)d_in[4];
    float*       out  = (float*)d_out;

    detect_kernel<<<1, 32>>>((const int*)ei);
    zero_cnt_kernel<<<(N_NODES + 255) / 256, 256>>>();
    hist_kernel<<<(N_EDGES + 255) / 256, 256>>>(ei);
    chunk_sum_kernel<<<NCH, CH>>>();
    scan_chunks_kernel<<<1, 1024>>>();
    write_off_kernel<<<NCH, CH>>>();
    fill_kernel<<<(N_EDGES + 255) / 256, 256>>>(ei);
    agg_kernel<<<(N_NODES * 32 + 255) / 256, 256>>>(x);

    {
        const int SMEM = 2 * BUF_FLOATS * sizeof(float);   // 137,216 B
        cudaFuncSetAttribute(gemm_mma,
                             cudaFuncAttributeMaxDynamicSharedMemorySize, SMEM);
        int blocks = (N_NODES + 127) / 128;                // 782
        gemm_mma<<<blocks, 512, SMEM>>>(x, W, R, bias, out);
    }
}

// round 10
// speedup vs baseline: 1.9810x; 1.0243x over previous
#include <cuda_runtime.h>
#include <cuda_bf16.h>
#include <cstdint>

#define N_NODES 100000
#define N_EDGES 1600000
#define D 128

#define CH 128
#define NCH ((N_NODES + CH - 1) / CH)   // 782

// ---------------- scratch (device globals; no allocation) -------------------
__device__ float g_agg[N_NODES * D];    // invd-scaled aggregated features
__device__ int   g_cnt[N_NODES];
__device__ int   g_off[N_NODES];
__device__ int   g_pos[N_NODES];
__device__ int   g_csr[N_EDGES];
__device__ int   g_chunk[NCH];
__device__ int   g_chunkoff[NCH];
__device__ int   g_is64;

__device__ __forceinline__ void cp16(void* dst, const void* src) {
    uint32_t d = (uint32_t)__cvta_generic_to_shared(dst);
    asm volatile("cp.async.cg.shared.global [%0], [%1], 16;" :: "r"(d), "l"(src));
}
__device__ __forceinline__ uint32_t f2tf32(float f) {
    uint32_t r;
    asm("cvt.rna.tf32.f32 %0, %1;" : "=r"(r) : "f"(f));
    return r;
}

// ---------------------------------------------------------------------------
__global__ void detect_kernel(const int* __restrict__ ei32) {
    if (threadIdx.x == 0 && blockIdx.x == 0) {
        int allzero = 1;
        for (int i = 0; i < 64; i++)
            if (ei32[2 * i + 1] != 0) { allzero = 0; break; }
        g_is64 = allzero;
    }
}

__global__ void zero_cnt_kernel() {
    int i = blockIdx.x * blockDim.x + threadIdx.x;
    if (i < N_NODES) g_cnt[i] = 0;
}

__global__ void hist_kernel(const void* __restrict__ ei_raw) {
    int e = blockIdx.x * blockDim.x + threadIdx.x;
    if (e >= N_EDGES) return;
    long long row = g_is64 ? ((const long long*)ei_raw)[e]
                           : (long long)((const int*)ei_raw)[e];
    if ((unsigned long long)row < N_NODES)
        atomicAdd(g_cnt + (int)row, 1);
}

__global__ __launch_bounds__(CH) void chunk_sum_kernel() {
    const int c = blockIdx.x;
    const int t = threadIdx.x;
    const int i = c * CH + t;
    int v = (i < N_NODES) ? g_cnt[i] : 0;
#pragma unroll
    for (int o = 16; o > 0; o >>= 1) v += __shfl_down_sync(~0u, v, o);
    __shared__ int ws[CH / 32];
    if ((t & 31) == 0) ws[t >> 5] = v;
    __syncthreads();
    if (t == 0) {
        int s = 0;
#pragma unroll
        for (int w = 0; w < CH / 32; w++) s += ws[w];
        g_chunk[c] = s;
    }
}

__global__ __launch_bounds__(1024) void scan_chunks_kernel() {
    __shared__ int tmp[1024];
    const int t = threadIdx.x;
    int v = (t < NCH) ? g_chunk[t] : 0;
    tmp[t] = v;
    __syncthreads();
    for (int o = 1; o < 1024; o <<= 1) {
        int u = (t >= o) ? tmp[t - o] : 0;
        __syncthreads();
        tmp[t] += u;
        __syncthreads();
    }
    if (t < NCH) g_chunkoff[t] = tmp[t] - v;
}

__global__ __launch_bounds__(CH) void write_off_kernel() {
    const int c = blockIdx.x;
    const int t = threadIdx.x;
    const int i = c * CH + t;
    const int lane = t & 31;
    const int w = t >> 5;
    int v = (i < N_NODES) ? g_cnt[i] : 0;

    int inc = v;
#pragma unroll
    for (int o = 1; o < 32; o <<= 1) {
        int u = __shfl_up_sync(~0u, inc, o);
        if (lane >= o) inc += u;
    }
    __shared__ int ws[CH / 32];
    __shared__ int wo[CH / 32];
    if (lane == 31) ws[w] = inc;
    __syncthreads();
    if (t == 0) {
        int run = 0;
#pragma unroll
        for (int k = 0; k < CH / 32; k++) { wo[k] = run; run += ws[k]; }
    }
    __syncthreads();
    int ex = inc - v + wo[w] + g_chunkoff[c];
    if (i < N_NODES) { g_off[i] = ex; g_pos[i] = ex; }
}

__global__ void fill_kernel(const void* __restrict__ ei_raw) {
    int e = blockIdx.x * blockDim.x + threadIdx.x;
    if (e >= N_EDGES) return;
    long long row, col;
    if (g_is64) {
        const long long* ei = (const long long*)ei_raw;
        row = ei[e]; col = ei[N_EDGES + e];
    } else {
        const int* ei = (const int*)ei_raw;
        row = ei[e]; col = ei[N_EDGES + e];
    }
    if ((unsigned long long)row >= N_NODES || (unsigned long long)col >= N_NODES)
        return;
    int p = atomicAdd(g_pos + (int)row, 1);
    g_csr[p] = (int)col;
}

// ---- gather-aggregate (invd folded in): one warp per node, unroll 4 ----
__global__ void agg_kernel(const float* __restrict__ x) {
    int n = (blockIdx.x * blockDim.x + threadIdx.x) >> 5;
    if (n >= N_NODES) return;
    const int lane = threadIdx.x & 31;
    const int start = g_off[n];
    const int cnt = g_cnt[n];

    float4 acc = make_float4(0.f, 0.f, 0.f, 0.f);
    int j = 0;
    for (; j + 4 <= cnt; j += 4) {
        int c0 = g_csr[start + j];
        int c1 = g_csr[start + j + 1];
        int c2 = g_csr[start + j + 2];
        int c3 = g_csr[start + j + 3];
        float4 v0 = __ldg((const float4*)(x + (long long)c0 * D + lane * 4));
        float4 v1 = __ldg((const float4*)(x + (long long)c1 * D + lane * 4));
        float4 v2 = __ldg((const float4*)(x + (long long)c2 * D + lane * 4));
        float4 v3 = __ldg((const float4*)(x + (long long)c3 * D + lane * 4));
        acc.x += (v0.x + v1.x) + (v2.x + v3.x);
        acc.y += (v0.y + v1.y) + (v2.y + v3.y);
        acc.z += (v0.z + v1.z) + (v2.z + v3.z);
        acc.w += (v0.w + v1.w) + (v2.w + v3.w);
    }
    for (; j < cnt; j++) {
        int c0 = g_csr[start + j];
        float4 v0 = __ldg((const float4*)(x + (long long)c0 * D + lane * 4));
        acc.x += v0.x; acc.y += v0.y; acc.z += v0.z; acc.w += v0.w;
    }
    const float invd = 1.0f / (float)max(cnt, 1);
    acc.x *= invd; acc.y *= invd; acc.z *= invd; acc.w *= invd;
    *reinterpret_cast<float4*>(g_agg + (long long)n * D + lane * 4) = acc;
}

// ---------------------------------------------------------------------------
// Pipelined tf32 GEMM: out = x @ R + agg_scaled @ W + bias.
// 4 K=64 stages, cp.async depth-2, THREE rotating buffers -> one sync/stage.
// Fragments rounded with cvt.rna.tf32 after LDS (restores rel_err ~3e-4).
// ---------------------------------------------------------------------------
#define APAD 68
#define BPAD 132
#define BUF_FLOATS (128 * APAD + 64 * BPAD)   // 17152

__global__ __launch_bounds__(512, 1) void gemm_mma(
    const float* __restrict__ x, const float* __restrict__ W,
    const float* __restrict__ R, const float* __restrict__ bias,
    float* __restrict__ out) {
    extern __shared__ float sm[];

    const int t = threadIdx.x;
    const int wid = t >> 5;
    const int lane = t & 31;
    const int wm = wid >> 2;
    const int wn = wid & 3;
    const int row0 = blockIdx.x * 128;
    const int lr = lane >> 2;
    const int lk = lane & 3;
    const int arow = wm * 32 + lr;
    const int bn = wn * 32 + lr;

    auto load_stage = [&](int s, int buf) {
        const float* Asrc = (s < 2) ? x : g_agg;
        const float* Bsrc = (s < 2) ? R : W;
        const int koff = (s & 1) * 64;
        float* dA = sm + buf * BUF_FLOATS;
        float* dB = dA + 128 * APAD;
#pragma unroll
        for (int v = t; v < 2048; v += 512) {
            int r = v >> 4;
            int k4 = (v & 15) << 2;
            int gr = row0 + r; if (gr >= N_NODES) gr = N_NODES - 1;
            cp16(dA + r * APAD + k4, Asrc + (long long)gr * D + koff + k4);
        }
#pragma unroll
        for (int v = t; v < 2048; v += 512) {
            int kr = v >> 5;
            int n4 = (v & 31) << 2;
            cp16(dB + kr * BPAD + n4, Bsrc + (koff + kr) * 128 + n4);
        }
        asm volatile("cp.async.commit_group;");
    };

    float c[2][4][4];
#pragma unroll
    for (int mt = 0; mt < 2; mt++)
#pragma unroll
        for (int nt = 0; nt < 4; nt++)
#pragma unroll
            for (int e = 0; e < 4; e++) c[mt][nt][e] = 0.f;

    load_stage(0, 0);
    load_stage(1, 1);

#pragma unroll
    for (int s = 0; s < 4; s++) {
        if (s < 3) asm volatile("cp.async.wait_group 1;");
        else       asm volatile("cp.async.wait_group 0;");
        __syncthreads();   // stage s data visible; all warps done with s-1

        if (s + 2 < 4) load_stage(s + 2, (s + 2) % 3);   // overlaps compute

        const float* bA = sm + (s % 3) * BUF_FLOATS;
        const float* bB = bA + 128 * APAD;

#pragma unroll
        for (int kc = 0; kc < 8; kc++) {
            const int kb = kc * 8;
            uint32_t a[2][4];
#pragma unroll
            for (int mt = 0; mt < 2; mt++) {
                int r_ = arow + mt * 16;
                a[mt][0] = f2tf32(bA[(r_    ) * APAD + kb + lk]);
                a[mt][1] = f2tf32(bA[(r_ + 8) * APAD + kb + lk]);
                a[mt][2] = f2tf32(bA[(r_    ) * APAD + kb + lk + 4]);
                a[mt][3] = f2tf32(bA[(r_ + 8) * APAD + kb + lk + 4]);
            }
            uint32_t b[4][2];
#pragma unroll
            for (int nt = 0; nt < 4; nt++) {
                b[nt][0] = f2tf32(bB[(kb + lk    ) * BPAD + bn + nt * 8]);
                b[nt][1] = f2tf32(bB[(kb + lk + 4) * BPAD + bn + nt * 8]);
            }
#pragma unroll
            for (int mt = 0; mt < 2; mt++)
#pragma unroll
                for (int nt = 0; nt < 4; nt++) {
                    asm volatile(
                        "mma.sync.aligned.m16n8k8.row.col.f32.tf32.tf32.f32 "
                        "{%0,%1,%2,%3}, {%4,%5,%6,%7}, {%8,%9}, {%0,%1,%2,%3};"
                        : "+f"(c[mt][nt][0]), "+f"(c[mt][nt][1]),
                          "+f"(c[mt][nt][2]), "+f"(c[mt][nt][3])
                        : "r"(a[mt][0]), "r"(a[mt][1]), "r"(a[mt][2]), "r"(a[mt][3]),
                          "r"(b[nt][0]), "r"(b[nt][1]));
                }
        }
    }

    // ---- epilogue ----
    const int lq = lane & 3;
#pragma unroll
    for (int mt = 0; mt < 2; mt++) {
#pragma unroll
        for (int nt = 0; nt < 4; nt++) {
            int cb = wn * 32 + nt * 8 + lq * 2;
            float2 bb = *reinterpret_cast<const float2*>(bias + cb);
            int r0 = row0 + wm * 32 + mt * 16 + lr;
            if (r0 < N_NODES) {
                float2 o = make_float2(c[mt][nt][0] + bb.x, c[mt][nt][1] + bb.y);
                *reinterpret_cast<float2*>(out + (long long)r0 * D + cb) = o;
            }
            int r1 = r0 + 8;
            if (r1 < N_NODES) {
                float2 o = make_float2(c[mt][nt][2] + bb.x, c[mt][nt][3] + bb.y);
                *reinterpret_cast<float2*>(out + (long long)r1 * D + cb) = o;
            }
        }
    }
}

// ---------------------------------------------------------------------------
extern "C" void kernel_launch(void* const* d_in, const int* in_sizes, int n_in,
                              void* d_out, int out_size) {
    const float* x    = (const float*)d_in[0];
    const void*  ei   = d_in[1];
    const float* W    = (const float*)d_in[2];
    const float* R    = (const float*)d_in[3];
    const float* bias = (const float*)d_in[4];
    float*       out  = (float*)d_out;

    detect_kernel<<<1, 32>>>((const int*)ei);
    zero_cnt_kernel<<<(N_NODES + 255) / 256, 256>>>();
    hist_kernel<<<(N_EDGES + 255) / 256, 256>>>(ei);
    chunk_sum_kernel<<<NCH, CH>>>();
    scan_chunks_kernel<<<1, 1024>>>();
    write_off_kernel<<<NCH, CH>>>();
    fill_kernel<<<(N_EDGES + 255) / 256, 256>>>(ei);
    agg_kernel<<<(N_NODES * 32 + 255) / 256, 256>>>(x);

    {
        const int SMEM = 3 * BUF_FLOATS * sizeof(float);   // 205,824 B
        cudaFuncSetAttribute(gemm_mma,
                             cudaFuncAttributeMaxDynamicSharedMemorySize, SMEM);
        int blocks = (N_NODES + 127) / 128;                // 782
        gemm_mma<<<blocks, 512, SMEM>>>(x, W, R, bias, out);
    }
}